// round 15
// baseline (speedup 1.0000x reference)
#include <cuda_runtime.h>

#define N_PTS   131072
#define K_CB    1024
#define NGRP    (K_CB / 4)   // 256 groups of 4 codes
#define D_DIM   10
#define CROW    12           // floats per code: e0..e9, esq, pad
#define THREADS 128
#define NSM     148
#define GRID    (NSM * 4)    // 592 CTAs -> 16 warps/SM
#define NWARP   (GRID * 4)   // 2368 warps
#define WTILES  (N_PTS / 32) // 4096 warp-tiles of 32 points
#define W2      (WTILES - NWARP)   // 1728 warps take 2 tiles, rest 1
#define BIGF    3.402823466e+38f

__constant__ float cEc[K_CB * CROW];          // 49152 B packed codebook
__device__   float g_stage[K_CB * CROW];
__device__   float g_partials[GRID];
__device__   unsigned int g_done = 0;

// ---- prep: pack codebook + esq into staging (copied to cEc) ----
__global__ void prep_kernel(const float* __restrict__ E) {
    const int tid = threadIdx.x;
    for (int k = tid; k < K_CB; k += 256) {
        float s = 0.f;
        for (int j = 0; j < D_DIM; j++) {
            float e = E[k * D_DIM + j];
            g_stage[k * CROW + j] = e;
            s = fmaf(e, e, s);
        }
        g_stage[k * CROW + 10] = s;
        g_stage[k * CROW + 11] = 0.f;
    }
}

// distance of point (xm2 = -2x) to code (uniform float4 triple), exact chain
__device__ __forceinline__ float code_dist(const float4& v0, const float4& v1,
                                           const float4& v2, const float* xm2) {
    float acc = v2.z;                         // esq (slot 10)
    acc = fmaf(xm2[0], v0.x, acc);
    acc = fmaf(xm2[1], v0.y, acc);
    acc = fmaf(xm2[2], v0.z, acc);
    acc = fmaf(xm2[3], v0.w, acc);
    acc = fmaf(xm2[4], v1.x, acc);
    acc = fmaf(xm2[5], v1.y, acc);
    acc = fmaf(xm2[6], v1.z, acc);
    acc = fmaf(xm2[7], v1.w, acc);
    acc = fmaf(xm2[8], v2.x, acc);
    acc = fmaf(xm2[9], v2.y, acc);
    return acc;
}

// Scan all code groups for PPT warp-tiles (this lane = one point per tile).
template <int PPT>
__device__ __forceinline__ float scan_points(
    const float* __restrict__ x, float* __restrict__ out, int wt0, int lane)
{
    const float4* cE4 = (const float4*)cEc;   // 3 float4 per code

    int n[PPT];
    #pragma unroll
    for (int q = 0; q < PPT; q++)
        n[q] = (wt0 + q) * 32 + lane;

    float xm2[PPT][D_DIM];
    #pragma unroll
    for (int q = 0; q < PPT; q++) {
        const float* xp = x + (size_t)n[q] * D_DIM;
        #pragma unroll
        for (int j = 0; j < D_DIM; j++)
            xm2[q][j] = -2.f * xp[j];
    }

    float best[PPT];
    int   bg[PPT];
    #pragma unroll
    for (int q = 0; q < PPT; q++) { best[q] = BIGF; bg[q] = 0; }

    #pragma unroll 1
    for (int p = 0; p < NGRP; ++p) {
        // 4 codes x 3 float4, uniform addresses -> LDCU/UR candidates
        float4 w0a = cE4[(p * 4 + 0) * 3 + 0];
        float4 w0b = cE4[(p * 4 + 0) * 3 + 1];
        float4 w0c = cE4[(p * 4 + 0) * 3 + 2];
        float4 w1a = cE4[(p * 4 + 1) * 3 + 0];
        float4 w1b = cE4[(p * 4 + 1) * 3 + 1];
        float4 w1c = cE4[(p * 4 + 1) * 3 + 2];
        float4 w2a = cE4[(p * 4 + 2) * 3 + 0];
        float4 w2b = cE4[(p * 4 + 2) * 3 + 1];
        float4 w2c = cE4[(p * 4 + 2) * 3 + 2];
        float4 w3a = cE4[(p * 4 + 3) * 3 + 0];
        float4 w3b = cE4[(p * 4 + 3) * 3 + 1];
        float4 w3c = cE4[(p * 4 + 3) * 3 + 2];

        #pragma unroll
        for (int q = 0; q < PPT; q++) {
            float d0 = code_dist(w0a, w0b, w0c, xm2[q]);
            float d1 = code_dist(w1a, w1b, w1c, xm2[q]);
            float d2 = code_dist(w2a, w2b, w2c, xm2[q]);
            float d3 = code_dist(w3a, w3b, w3c, xm2[q]);
            float m = fminf(fminf(d0, d1), fminf(d2, d3));
            if (m < best[q]) { best[q] = m; bg[q] = p; }   // strict < = first min
        }
    }

    // resolve winning code in group (bit-exact recompute, ascending first-min)
    float part = 0.f;
    #pragma unroll
    for (int q = 0; q < PPT; q++) {
        const int p = bg[q];
        float dmin = BIGF;
        int kb = 0;
        #pragma unroll
        for (int c = 0; c < 4; c++) {
            float4 va = cE4[(p * 4 + c) * 3 + 0];
            float4 vb = cE4[(p * 4 + c) * 3 + 1];
            float4 vc = cE4[(p * 4 + c) * 3 + 2];
            float d = code_dist(va, vb, vc, xm2[q]);
            if (d < dmin) { dmin = d; kb = p * 4 + c; }    // ascending, strict <
        }

        const float* er = cEc + kb * CROW;
        float* o = out + (size_t)n[q] * D_DIM;
        #pragma unroll
        for (int j = 0; j < D_DIM; j++) {
            float qv = er[j];
            o[j] = qv;
            float xv = -0.5f * xm2[q][j];                  // exact recover x
            float dd = xv - qv;
            part = fmaf(dd, dd, part);
        }
    }
    return part;
}

__global__ void __launch_bounds__(THREADS, 4)
vq_kernel(const float* __restrict__ x,      // [N, D]
          float* __restrict__ out)          // [N*D] quantized + loss slot
{
    __shared__ float sred[THREADS / 32];
    __shared__ int   s_last;

    const int tid  = threadIdx.x;
    const int bid  = blockIdx.x;
    const int wid  = tid >> 5;
    const int lane = tid & 31;

    // --- per-warp balanced tile assignment: warps < W2 take 2 tiles, else 1 ---
    const int g = bid * 4 + wid;
    int wt0, cnt;
    if (g < W2) { cnt = 2; wt0 = g * 2; }
    else        { cnt = 1; wt0 = W2 * 2 + (g - W2); }

    float part;
    if (cnt == 2)
        part = scan_points<2>(x, out, wt0, lane);
    else
        part = scan_points<1>(x, out, wt0, lane);

    // --- deterministic loss: warp reduce -> CTA reduce -> per-CTA partial ---
    #pragma unroll
    for (int offr = 16; offr > 0; offr >>= 1)
        part += __shfl_down_sync(0xFFFFFFFFu, part, offr);
    if (lane == 0) sred[wid] = part;
    __syncthreads();

    if (tid == 0) {
        float s = sred[0] + sred[1] + sred[2] + sred[3];
        g_partials[bid] = s;
        __threadfence();
        unsigned int old = atomicAdd(&g_done, 1u);
        s_last = (old == GRID - 1) ? 1 : 0;
    }
    __syncthreads();

    // --- last CTA finalizes loss (fixed order -> deterministic) ---
    if (s_last) {
        __shared__ float sfin[THREADS];
        float s = 0.f;
        for (int r = tid; r < GRID; r += THREADS)   // fixed strided order
            s += g_partials[r];
        sfin[tid] = s;
        __syncthreads();
        #pragma unroll
        for (int o = THREADS / 2; o > 0; o >>= 1) {
            if (tid < o) sfin[tid] += sfin[tid + o];
            __syncthreads();
        }
        if (tid == 0) {
            out[(size_t)N_PTS * D_DIM] = sfin[0] * (1.0f / ((float)N_PTS * (float)D_DIM));
            g_done = 0;   // reset for next graph replay
        }
    }
}

extern "C" void kernel_launch(void* const* d_in, const int* in_sizes, int n_in,
                              void* d_out, int out_size) {
    const float* x = (const float*)d_in[0];   // encoder_embedding [N, D]
    const float* E = (const float*)d_in[1];   // embedding_weight  [K, D]
    float* out = (float*)d_out;

    prep_kernel<<<1, 256>>>(E);

    void* stage_ptr = nullptr;
    cudaGetSymbolAddress(&stage_ptr, g_stage);                    // no alloc
    cudaMemcpyToSymbolAsync(cEc, stage_ptr, sizeof(float) * K_CB * CROW,
                            0, cudaMemcpyDeviceToDevice);          // D2D, capturable

    vq_kernel<<<GRID, THREADS>>>(x, out);
}

// round 16
// speedup vs baseline: 6.6934x; 6.6934x over previous
#include <cuda_runtime.h>

#define N_PTS   131072
#define K_CB    1024
#define NPAIR   512          // K_CB / 2
#define D_DIM   10
#define PROW    20           // floats per code-pair row: 10 dims x f32x2
#define THREADS 128
#define NSM     148
#define GRID    (NSM * 2)    // 296 CTAs: 2 per SM, 2 warps per SMSP
#define WARPS   (GRID * 4)   // 1184 warp-scans
#define WTILES  (N_PTS / 32) // 4096 warp-tiles of 32 points
#define W4      (WTILES - 3 * WARPS)   // 544 warps take 4 tiles, rest take 3

__device__ float        g_partials[GRID];
__device__ unsigned int g_done = 0;

__device__ __forceinline__ unsigned long long fma2(
    unsigned long long a, unsigned long long b, unsigned long long c) {
    unsigned long long d;
    asm("fma.rn.f32x2 %0, %1, %2, %3;" : "=l"(d) : "l"(a), "l"(b), "l"(c));
    return d;
}
__device__ __forceinline__ unsigned long long dup2(float v) {
    unsigned long long r;
    asm("mov.b64 %0, {%1, %1};" : "=l"(r) : "f"(v));
    return r;
}
__device__ __forceinline__ void unpack2(unsigned long long v, float& lo, float& hi) {
    asm("mov.b64 {%0, %1}, %2;" : "=f"(lo), "=f"(hi) : "l"(v));
}

// Bit-exact distance pair for one code-pair row (same FMA order as hot loop).
__device__ __forceinline__ void pair_dists(const ulonglong2* w,
                                           unsigned long long esq,
                                           const unsigned long long* xd,
                                           float& d0, float& d1) {
    ulonglong2 c0 = w[0], c1 = w[1], c2 = w[2], c3 = w[3], c4 = w[4];
    unsigned long long a = esq;
    a = fma2(c0.x, xd[0], a);
    a = fma2(c0.y, xd[1], a);
    a = fma2(c1.x, xd[2], a);
    a = fma2(c1.y, xd[3], a);
    a = fma2(c2.x, xd[4], a);
    a = fma2(c2.y, xd[5], a);
    a = fma2(c3.x, xd[6], a);
    a = fma2(c3.y, xd[7], a);
    a = fma2(c4.x, xd[8], a);
    a = fma2(c4.y, xd[9], a);
    unpack2(a, d0, d1);
}

// Scan all code pairs for PPT warp-tiles (this lane = one point per tile).
template <int PPT>
__device__ __forceinline__ float scan_points(
    const float* __restrict__ x, float* __restrict__ out,
    const float* sE, const float* sEsq, int wt0, int lane)
{
    int n[PPT];
    #pragma unroll
    for (int q = 0; q < PPT; q++)
        n[q] = (wt0 + q) * 32 + lane;

    unsigned long long xd[PPT][D_DIM];
    #pragma unroll
    for (int q = 0; q < PPT; q++) {
        const float* xp = x + (size_t)n[q] * D_DIM;
        #pragma unroll
        for (int j = 0; j < D_DIM; j++)
            xd[q][j] = dup2(-2.f * xp[j]);
    }

    float best[PPT];
    int   bp[PPT];
    #pragma unroll
    for (int q = 0; q < PPT; q++) { best[q] = 3.402823466e+38f; bp[q] = 0; }

    const ulonglong2* dims = (const ulonglong2*)sE;          // 5 per pair row
    const unsigned long long* esqp = (const unsigned long long*)sEsq;

    // software-pipelined: prime pair 0
    ulonglong2 c0 = dims[0], c1 = dims[1], c2 = dims[2], c3 = dims[3], c4 = dims[4];
    unsigned long long esq = esqp[0];

    for (int p = 0; p < NPAIR; ++p) {
        const int pn = (p + 1) & (NPAIR - 1);
        const ulonglong2* wn = dims + (size_t)pn * 5;
        ulonglong2 n0 = wn[0], n1 = wn[1], n2 = wn[2], n3 = wn[3], n4 = wn[4];
        unsigned long long esqn = esqp[pn];

        #pragma unroll
        for (int q = 0; q < PPT; q++) {
            unsigned long long a = esq;
            a = fma2(c0.x, xd[q][0], a);
            a = fma2(c0.y, xd[q][1], a);
            a = fma2(c1.x, xd[q][2], a);
            a = fma2(c1.y, xd[q][3], a);
            a = fma2(c2.x, xd[q][4], a);
            a = fma2(c2.y, xd[q][5], a);
            a = fma2(c3.x, xd[q][6], a);
            a = fma2(c3.y, xd[q][7], a);
            a = fma2(c4.x, xd[q][8], a);
            a = fma2(c4.y, xd[q][9], a);
            float d0, d1;
            unpack2(a, d0, d1);
            float m = fminf(d0, d1);                   // FMNMX (alu pipe)
            if (m < best[q]) { best[q] = m; bp[q] = p; }   // strict < = first min
        }
        c0 = n0; c1 = n1; c2 = n2; c3 = n3; c4 = n4; esq = esqn;
    }

    // resolve winning lane (bit-exact recompute), write out + loss
    float part = 0.f;
    #pragma unroll
    for (int q = 0; q < PPT; q++) {
        int p = bp[q];
        float d0, d1;
        pair_dists(dims + (size_t)p * 5, esqp[p], xd[q], d0, d1);
        int lsel = (d1 < d0) ? 1 : 0;                  // tie -> lane 0 (lower k)
        const float* er = sE + p * PROW;
        float* o = out + (size_t)n[q] * D_DIM;
        #pragma unroll
        for (int j = 0; j < D_DIM; j++) {
            float qv = er[2 * j + lsel];
            o[j] = qv;
            float lo, hi;
            unpack2(xd[q][j], lo, hi);
            float xv = -0.5f * lo;                     // exact: (-0.5)*(-2x) = x
            float dd = xv - qv;
            part += dd * dd;
        }
    }
    return part;
}

__global__ void __launch_bounds__(THREADS, 2)
vq_kernel(const float* __restrict__ x,      // [N, D]
          const float* __restrict__ E,      // [K, D]
          float* __restrict__ out)          // [N*D] quantized + loss slot
{
    __shared__ float sE[NPAIR * PROW];      // 40960 B pair-packed dims (f32x2 layout)
    __shared__ float sEsq[K_CB];            //  4096 B (esq0,esq1) adjacent pairs
    __shared__ float sred[THREADS / 32];
    __shared__ int   s_last;

    const int tid  = threadIdx.x;
    const int bid  = blockIdx.x;
    const int wid  = tid >> 5;
    const int lane = tid & 31;

    // --- fused prologue: each thread owns whole codes; float2 gmem loads,
    //     esq computed from registers, single sync ---
    #pragma unroll
    for (int k = tid; k < K_CB; k += THREADS) {
        const float2* row = (const float2*)(E + (size_t)k * D_DIM);  // 8B aligned
        float2 r0 = row[0], r1 = row[1], r2 = row[2], r3 = row[3], r4 = row[4];
        const int p = k >> 1, l = k & 1;
        float* dst = sE + p * PROW + l;
        dst[0]  = r0.x;  dst[2]  = r0.y;
        dst[4]  = r1.x;  dst[6]  = r1.y;
        dst[8]  = r2.x;  dst[10] = r2.y;
        dst[12] = r3.x;  dst[14] = r3.y;
        dst[16] = r4.x;  dst[18] = r4.y;
        float s = r0.x * r0.x;
        s = fmaf(r0.y, r0.y, s);
        s = fmaf(r1.x, r1.x, s);
        s = fmaf(r1.y, r1.y, s);
        s = fmaf(r2.x, r2.x, s);
        s = fmaf(r2.y, r2.y, s);
        s = fmaf(r3.x, r3.x, s);
        s = fmaf(r3.y, r3.y, s);
        s = fmaf(r4.x, r4.x, s);
        s = fmaf(r4.y, r4.y, s);
        sEsq[k] = s;
    }
    __syncthreads();

    // --- per-warp balanced tile assignment ---
    const int g = bid * 4 + wid;
    int wt0, cnt;
    if (g < W4) { cnt = 4; wt0 = g * 4; }
    else        { cnt = 3; wt0 = W4 * 4 + (g - W4) * 3; }

    float part;
    if (cnt == 4)
        part = scan_points<4>(x, out, sE, sEsq, wt0, lane);
    else
        part = scan_points<3>(x, out, sE, sEsq, wt0, lane);

    // --- deterministic loss: warp reduce -> CTA reduce -> per-CTA partial ---
    #pragma unroll
    for (int offr = 16; offr > 0; offr >>= 1)
        part += __shfl_down_sync(0xFFFFFFFFu, part, offr);
    if (lane == 0) sred[wid] = part;
    __syncthreads();

    if (tid == 0) {
        float s = sred[0] + sred[1] + sred[2] + sred[3];
        g_partials[bid] = s;
        __threadfence();
        unsigned int old = atomicAdd(&g_done, 1u);
        s_last = (old == GRID - 1) ? 1 : 0;
    }
    __syncthreads();

    // --- last CTA finalizes loss (fixed order -> deterministic) ---
    if (s_last) {
        __shared__ float sfin[THREADS];
        float s = 0.f;
        for (int r = tid; r < GRID; r += THREADS)   // fixed strided order
            s += g_partials[r];
        sfin[tid] = s;
        __syncthreads();
        #pragma unroll
        for (int o = THREADS / 2; o > 0; o >>= 1) {
            if (tid < o) sfin[tid] += sfin[tid + o];
            __syncthreads();
        }
        if (tid == 0) {
            out[(size_t)N_PTS * D_DIM] = sfin[0] * (1.0f / ((float)N_PTS * (float)D_DIM));
            g_done = 0;   // reset for next graph replay
        }
    }
}

extern "C" void kernel_launch(void* const* d_in, const int* in_sizes, int n_in,
                              void* d_out, int out_size) {
    const float* x = (const float*)d_in[0];   // encoder_embedding [N, D]
    const float* E = (const float*)d_in[1];   // embedding_weight  [K, D]
    float* out = (float*)d_out;

    vq_kernel<<<GRID, THREADS>>>(x, E, out);
}

// round 17
// speedup vs baseline: 6.8875x; 1.0290x over previous
#include <cuda_runtime.h>

#define N_PTS   131072
#define K_CB    1024
#define NPAIR   512          // K_CB / 2
#define NBLK    256          // blocks of 2 pairs (4 codes)
#define D_DIM   10
#define PROW    20           // floats per code-pair row: 10 dims x f32x2
#define THREADS 128
#define NSM     148
#define GRID    (NSM * 2)    // 296 CTAs: 2 per SM, 2 warps per SMSP
#define WARPS   (GRID * 4)   // 1184 warp-scans
#define WTILES  (N_PTS / 32) // 4096 warp-tiles of 32 points
#define W4      (WTILES - 3 * WARPS)   // 544 warps take 4 tiles, rest take 3

__device__ float        g_partials[GRID];
__device__ unsigned int g_done = 0;

__device__ __forceinline__ unsigned long long fma2(
    unsigned long long a, unsigned long long b, unsigned long long c) {
    unsigned long long d;
    asm("fma.rn.f32x2 %0, %1, %2, %3;" : "=l"(d) : "l"(a), "l"(b), "l"(c));
    return d;
}
__device__ __forceinline__ unsigned long long dup2(float v) {
    unsigned long long r;
    asm("mov.b64 %0, {%1, %1};" : "=l"(r) : "f"(v));
    return r;
}
__device__ __forceinline__ void unpack2(unsigned long long v, float& lo, float& hi) {
    asm("mov.b64 {%0, %1}, %2;" : "=f"(lo), "=f"(hi) : "l"(v));
}

// Bit-exact distance pair for one code-pair row (same FMA order as hot loop).
__device__ __forceinline__ void pair_dists(const ulonglong2* w,
                                           unsigned long long esq,
                                           const unsigned long long* xd,
                                           float& d0, float& d1) {
    ulonglong2 c0 = w[0], c1 = w[1], c2 = w[2], c3 = w[3], c4 = w[4];
    unsigned long long a = esq;
    a = fma2(c0.x, xd[0], a);
    a = fma2(c0.y, xd[1], a);
    a = fma2(c1.x, xd[2], a);
    a = fma2(c1.y, xd[3], a);
    a = fma2(c2.x, xd[4], a);
    a = fma2(c2.y, xd[5], a);
    a = fma2(c3.x, xd[6], a);
    a = fma2(c3.y, xd[7], a);
    a = fma2(c4.x, xd[8], a);
    a = fma2(c4.y, xd[9], a);
    unpack2(a, d0, d1);
}

// Scan all 2-pair blocks for PPT warp-tiles (this lane = one point per tile).
template <int PPT>
__device__ __forceinline__ float scan_points(
    const float* __restrict__ x, float* __restrict__ out,
    const float* sE, const float* sEsq, int wt0, int lane)
{
    int n[PPT];
    #pragma unroll
    for (int q = 0; q < PPT; q++)
        n[q] = (wt0 + q) * 32 + lane;

    unsigned long long xd[PPT][D_DIM];
    #pragma unroll
    for (int q = 0; q < PPT; q++) {
        const float* xp = x + (size_t)n[q] * D_DIM;
        #pragma unroll
        for (int j = 0; j < D_DIM; j++)
            xd[q][j] = dup2(-2.f * xp[j]);
    }

    float best[PPT];
    int   bt[PPT];
    #pragma unroll
    for (int q = 0; q < PPT; q++) { best[q] = 3.402823466e+38f; bt[q] = 0; }

    const ulonglong2* dims = (const ulonglong2*)sE;          // 5 per pair row
    const ulonglong2* esq4 = (const ulonglong2*)sEsq;        // 4 esq per block

    // software-pipelined: prime block 0 (pairs 0,1)
    ulonglong2 a0 = dims[0], a1 = dims[1], a2 = dims[2], a3 = dims[3], a4 = dims[4];
    ulonglong2 b0 = dims[5], b1 = dims[6], b2 = dims[7], b3 = dims[8], b4 = dims[9];
    ulonglong2 eq = esq4[0];

    for (int t = 0; t < NBLK; ++t) {
        const int tn = (t + 1) & (NBLK - 1);
        const ulonglong2* wn = dims + (size_t)tn * 10;
        ulonglong2 na0 = wn[0], na1 = wn[1], na2 = wn[2], na3 = wn[3], na4 = wn[4];
        ulonglong2 nb0 = wn[5], nb1 = wn[6], nb2 = wn[7], nb3 = wn[8], nb4 = wn[9];
        ulonglong2 neq = esq4[tn];

        #pragma unroll
        for (int q = 0; q < PPT; q++) {
            unsigned long long aa = eq.x;              // (esq0, esq1)
            aa = fma2(a0.x, xd[q][0], aa);
            aa = fma2(a0.y, xd[q][1], aa);
            aa = fma2(a1.x, xd[q][2], aa);
            aa = fma2(a1.y, xd[q][3], aa);
            aa = fma2(a2.x, xd[q][4], aa);
            aa = fma2(a2.y, xd[q][5], aa);
            aa = fma2(a3.x, xd[q][6], aa);
            aa = fma2(a3.y, xd[q][7], aa);
            aa = fma2(a4.x, xd[q][8], aa);
            aa = fma2(a4.y, xd[q][9], aa);

            unsigned long long ab = eq.y;              // (esq2, esq3)
            ab = fma2(b0.x, xd[q][0], ab);
            ab = fma2(b0.y, xd[q][1], ab);
            ab = fma2(b1.x, xd[q][2], ab);
            ab = fma2(b1.y, xd[q][3], ab);
            ab = fma2(b2.x, xd[q][4], ab);
            ab = fma2(b2.y, xd[q][5], ab);
            ab = fma2(b3.x, xd[q][6], ab);
            ab = fma2(b3.y, xd[q][7], ab);
            ab = fma2(b4.x, xd[q][8], ab);
            ab = fma2(b4.y, xd[q][9], ab);

            float dA0, dA1, dB0, dB1;
            unpack2(aa, dA0, dA1);
            unpack2(ab, dB0, dB1);
            float mm = fminf(fminf(dA0, dA1), fminf(dB0, dB1));   // 3 FMNMX
            if (mm < best[q]) { best[q] = mm; bt[q] = t; }  // strict < = first min
        }
        a0 = na0; a1 = na1; a2 = na2; a3 = na3; a4 = na4;
        b0 = nb0; b1 = nb1; b2 = nb2; b3 = nb3; b4 = nb4;
        eq = neq;
    }

    // resolve winning code within block (bit-exact recompute, ascending k,
    // strict < keeps first min), write out + loss
    float part = 0.f;
    #pragma unroll
    for (int q = 0; q < PPT; q++) {
        const int t = bt[q];
        const ulonglong2* wb = dims + (size_t)t * 10;
        ulonglong2 e4 = esq4[t];
        float dA0, dA1, dB0, dB1;
        pair_dists(wb,     e4.x, xd[q], dA0, dA1);
        pair_dists(wb + 5, e4.y, xd[q], dB0, dB1);

        // ascending-k first-min over the 4 codes of this block
        float dm = dA0; int ksel = 0;
        if (dA1 < dm) { dm = dA1; ksel = 1; }
        if (dB0 < dm) { dm = dB0; ksel = 2; }
        if (dB1 < dm) { dm = dB1; ksel = 3; }

        const int p    = 2 * t + (ksel >> 1);          // winning pair row
        const int lsel = ksel & 1;                     // lane within pair
        const float* er = sE + p * PROW;
        float* o = out + (size_t)n[q] * D_DIM;
        #pragma unroll
        for (int j = 0; j < D_DIM; j++) {
            float qv = er[2 * j + lsel];
            o[j] = qv;
            float lo, hi;
            unpack2(xd[q][j], lo, hi);
            float xv = -0.5f * lo;                     // exact: (-0.5)*(-2x) = x
            float dd = xv - qv;
            part += dd * dd;
        }
    }
    return part;
}

__global__ void __launch_bounds__(THREADS, 2)
vq_kernel(const float* __restrict__ x,      // [N, D]
          const float* __restrict__ E,      // [K, D]
          float* __restrict__ out)          // [N*D] quantized + loss slot
{
    __shared__ float sE[NPAIR * PROW];      // 40960 B pair-packed dims (f32x2 layout)
    __shared__ float sEsq[K_CB];            //  4096 B esq[k], 16B-aligned blocks of 4
    __shared__ float sred[THREADS / 32];
    __shared__ int   s_last;

    const int tid  = threadIdx.x;
    const int bid  = blockIdx.x;
    const int wid  = tid >> 5;
    const int lane = tid & 31;

    // --- fused prologue: each thread owns whole codes; float2 gmem loads,
    //     esq computed from registers, single sync ---
    #pragma unroll
    for (int k = tid; k < K_CB; k += THREADS) {
        const float2* row = (const float2*)(E + (size_t)k * D_DIM);  // 8B aligned
        float2 r0 = row[0], r1 = row[1], r2 = row[2], r3 = row[3], r4 = row[4];
        const int p = k >> 1, l = k & 1;
        float* dst = sE + p * PROW + l;
        dst[0]  = r0.x;  dst[2]  = r0.y;
        dst[4]  = r1.x;  dst[6]  = r1.y;
        dst[8]  = r2.x;  dst[10] = r2.y;
        dst[12] = r3.x;  dst[14] = r3.y;
        dst[16] = r4.x;  dst[18] = r4.y;
        float s = r0.x * r0.x;
        s = fmaf(r0.y, r0.y, s);
        s = fmaf(r1.x, r1.x, s);
        s = fmaf(r1.y, r1.y, s);
        s = fmaf(r2.x, r2.x, s);
        s = fmaf(r2.y, r2.y, s);
        s = fmaf(r3.x, r3.x, s);
        s = fmaf(r3.y, r3.y, s);
        s = fmaf(r4.x, r4.x, s);
        s = fmaf(r4.y, r4.y, s);
        sEsq[k] = s;
    }
    __syncthreads();

    // --- per-warp balanced tile assignment ---
    const int g = bid * 4 + wid;
    int wt0, cnt;
    if (g < W4) { cnt = 4; wt0 = g * 4; }
    else        { cnt = 3; wt0 = W4 * 4 + (g - W4) * 3; }

    float part;
    if (cnt == 4)
        part = scan_points<4>(x, out, sE, sEsq, wt0, lane);
    else
        part = scan_points<3>(x, out, sE, sEsq, wt0, lane);

    // --- deterministic loss: warp reduce -> CTA reduce -> per-CTA partial ---
    #pragma unroll
    for (int offr = 16; offr > 0; offr >>= 1)
        part += __shfl_down_sync(0xFFFFFFFFu, part, offr);
    if (lane == 0) sred[wid] = part;
    __syncthreads();

    if (tid == 0) {
        float s = sred[0] + sred[1] + sred[2] + sred[3];
        g_partials[bid] = s;
        __threadfence();
        unsigned int old = atomicAdd(&g_done, 1u);
        s_last = (old == GRID - 1) ? 1 : 0;
    }
    __syncthreads();

    // --- last CTA finalizes loss (fixed order -> deterministic) ---
    if (s_last) {
        __shared__ float sfin[THREADS];
        float s = 0.f;
        for (int r = tid; r < GRID; r += THREADS)   // fixed strided order
            s += g_partials[r];
        sfin[tid] = s;
        __syncthreads();
        #pragma unroll
        for (int o = THREADS / 2; o > 0; o >>= 1) {
            if (tid < o) sfin[tid] += sfin[tid + o];
            __syncthreads();
        }
        if (tid == 0) {
            out[(size_t)N_PTS * D_DIM] = sfin[0] * (1.0f / ((float)N_PTS * (float)D_DIM));
            g_done = 0;   // reset for next graph replay
        }
    }
}

extern "C" void kernel_launch(void* const* d_in, const int* in_sizes, int n_in,
                              void* d_out, int out_size) {
    const float* x = (const float*)d_in[0];   // encoder_embedding [N, D]
    const float* E = (const float*)d_in[1];   // embedding_weight  [K, D]
    float* out = (float*)d_out;

    vq_kernel<<<GRID, THREADS>>>(x, E, out);
}